// round 15
// baseline (speedup 1.0000x reference)
#include <cuda_runtime.h>
#include <cstdint>

// Embedding gather: out[i, :] = weight[indices[i], :]
// 819200 rows x 64 fp32 = 256B/row. 8 threads/row with 256-bit ops.
//
// FINAL v15 = v12 (measured best, 62.7-63.1us) + compile-time-constant grid
// shape: stride/grid hardcoded for the 819200-row case, removing the
// gridDim read + stride multiply and folding addressing into 32-bit math.
//
// Configuration: UNROLL=2 x 256-thread blocks x 12800 blocks, 28 regs,
// occ ~81%; two genuinely concurrent 256-bit evict_last gathers per thread,
// 256-bit evict_first streaming stores, exact division, zero predication.
//
// Roofline evidence (v5-v14: LDG.128/LDG.256/cp.async, occ 41-83%, three L2
// policies, regs 28-46): all land at 62.7-63.8us = ~335MB irreducible traffic
// (210MB mandatory fp32 writes + ~122MB unique random 256B reads + 3MB idx)
// at ~5.3 TB/s sustained mixed-stream HBM bandwidth. This is the floor.

static constexpr int UNROLL = 2;

// Fixed shape for the fast path: 819200 rows -> 6,553,600 32B-segments.
static constexpr unsigned FIX_THREADS = 256;
static constexpr unsigned FIX_BLOCKS  = 12800;
static constexpr unsigned FIX_STRIDE  = FIX_THREADS * FIX_BLOCKS;  // 3,276,800

struct V8 { uint32_t r[8]; };

__device__ __forceinline__ V8 ldg256_evict_last(const uint32_t* p) {
    V8 v;
    asm volatile("ld.global.nc.L2::evict_last.v8.b32 {%0,%1,%2,%3,%4,%5,%6,%7}, [%8];"
                 : "=r"(v.r[0]), "=r"(v.r[1]), "=r"(v.r[2]), "=r"(v.r[3]),
                   "=r"(v.r[4]), "=r"(v.r[5]), "=r"(v.r[6]), "=r"(v.r[7])
                 : "l"(p));
    return v;
}

__device__ __forceinline__ void stg256_evict_first(uint32_t* p, const V8& v) {
    asm volatile("st.global.L2::evict_first.v8.b32 [%0], {%1,%2,%3,%4,%5,%6,%7,%8};"
                 :: "l"(p),
                    "r"(v.r[0]), "r"(v.r[1]), "r"(v.r[2]), "r"(v.r[3]),
                    "r"(v.r[4]), "r"(v.r[5]), "r"(v.r[6]), "r"(v.r[7]));
}

// Fixed-shape path: all shape arithmetic is compile-time constant / 32-bit.
__global__ __launch_bounds__(FIX_THREADS)
void embed_gather_fixed(const int* __restrict__ indices,
                        const uint32_t* __restrict__ weight,
                        uint32_t* __restrict__ out)
{
    const unsigned base = blockIdx.x * FIX_THREADS + threadIdx.x;  // < 2^22
    const unsigned seg  = base & 7;                 // 32B segment within row

    const unsigned row0       = base >> 3;
    const unsigned row_stride = FIX_STRIDE >> 3;    // immediate: 409,600

    // Batch 1: independent index loads (8-lane broadcast, L1 hits)
    int idx[UNROLL];
#pragma unroll
    for (int k = 0; k < UNROLL; k++)
        idx[k] = __ldg(indices + row0 + k * row_stride);

    // Batch 2: two genuinely concurrent 256-bit gathers per thread
    V8 v[UNROLL];
#pragma unroll
    for (int k = 0; k < UNROLL; k++)
        v[k] = ldg256_evict_last(weight + (long long)idx[k] * 64 + seg * 8);

    // Batch 3: 256-bit streaming stores, evict-first (output never re-read)
#pragma unroll
    for (int k = 0; k < UNROLL; k++)
        stg256_evict_first(out + ((long long)base + (long long)k * FIX_STRIDE) * 8, v[k]);
}

// General fallback: 128-bit, predicated, no hints (any shape).
__global__ __launch_bounds__(256)
void embed_gather_general(const int* __restrict__ indices,
                          const float4* __restrict__ weight,
                          float4* __restrict__ out,
                          long long total_vec)   // float4 count
{
    const long long stride = (long long)gridDim.x * blockDim.x;
    const long long base   = (long long)blockIdx.x * blockDim.x + threadIdx.x;

    for (long long p = base; p < total_vec; p += stride) {
        int idx = __ldg(indices + (p >> 4));
        float4 v = __ldg(weight + (long long)idx * 16 + (p & 15));
        __stcs(out + p, v);
    }
}

extern "C" void kernel_launch(void* const* d_in, const int* in_sizes, int n_in,
                              void* d_out, int out_size)
{
    const int* indices  = (const int*)d_in[0];     // 819200 int32
    long long  num_rows = in_sizes[0];

    long long total_vec256 = num_rows * 8;

    if (total_vec256 == (long long)FIX_STRIDE * UNROLL) {   // 6,553,600
        embed_gather_fixed<<<FIX_BLOCKS, FIX_THREADS>>>(
            indices, (const uint32_t*)d_in[1], (uint32_t*)d_out);
    } else {
        long long total_vec = num_rows * 16;
        int blocks = (int)((total_vec + 511) / 512);
        embed_gather_general<<<blocks, 256>>>(
            indices, (const float4*)d_in[1], (float4*)d_out, total_vec);
    }
}